// round 1
// baseline (speedup 1.0000x reference)
#include <cuda_runtime.h>

// Problem constants (fixed by the reference)
#define BATCH 16
#define MCTRL 64          // control points per dim
#define DEG   3           // degree P == Q
#define KLEN  68          // MCTRL + DEG + 1 knots
#define NSPAN 62          // KLEN - 2*DEG candidate spans
#define TPTS  256         // OUT_U == OUT_V

// Scratch (no allocations allowed): basis [B][T][4], span [B][T]
__device__ float g_basis[BATCH * TPTS * 4];
__device__ int   g_span [BATCH * TPTS];

// ---------------------------------------------------------------------------
// Kernel 1: normalize knots (cumsum), find spans, Cox-de Boor basis (deg 3).
// One block per batch, one thread per eval point. Nv==Nu (reference reuses
// knot_u for V and u==v), so one table serves both directions.
// ---------------------------------------------------------------------------
__global__ void basis_kernel(const float* __restrict__ knot_u) {
    __shared__ float c[KLEN];   // cumsum
    __shared__ float U[KLEN];   // normalized knots
    const int b = blockIdx.x;
    const int t = threadIdx.x;

    if (t < KLEN) c[t] = knot_u[b * KLEN + t];
    __syncthreads();
    if (t == 0) {
        float s = 0.0f;
        for (int i = 0; i < KLEN; i++) { s += c[i]; c[i] = s; }
    }
    __syncthreads();
    {
        const float c0 = c[0];
        const float inv = 1.0f / (c[KLEN - 1] - c0);
        if (t < KLEN) U[t] = (c[t] - c0) * inv;
    }
    __syncthreads();

    // Parameter value: linspace(1e-5, 1-1e-5, 256)
    const float tp = 1e-5f + (float)t * ((1.0f - 2e-5f) / 255.0f);

    // Span: argmin over candidates (first minimum, like jnp.argmin)
    float best = 1e30f;
    int   bs   = 0;
    #pragma unroll 1
    for (int s = 0; s < NSPAN; s++) {
        float d    = tp - U[DEG + s];
        float cand = (d > 1e-8f) ? d : 1.0f;
        if (cand < best) { best = cand; bs = s; }
    }
    const int span = bs + DEG;

    // Cox-de Boor recursion, deg 3 — exactly the reference arithmetic.
    float N[DEG + 1];
    N[0] = 1.0f;
    #pragma unroll
    for (int k = 1; k <= DEG; k++) {
        float saved = 0.0f;
        #pragma unroll
        for (int r = 0; r < k; r++) {
            const float K1 = U[span + r + 1];
            const float K2 = U[span + 1 - k + r];
            const float temp = N[r] / ((K1 - tp) + (tp - K2));
            N[r] = saved + (K1 - tp) * temp;
            saved = (tp - K2) * temp;
        }
        N[k] = saved;
    }

    const int base = b * TPTS + t;
    #pragma unroll
    for (int l = 0; l <= DEG; l++) g_basis[base * 4 + l] = N[l];
    g_span[base] = span;
}

// ---------------------------------------------------------------------------
// Kernel 2: surface evaluation.
// Block = (i, b): one output row. 256 threads, one per j.
// Stage the 4 control rows for this i (4 x 64 float4 = 4KB) in shared —
// exactly one float4 global load per thread — then 16 LDS.128 + 48 FMA per
// output point. Writes 3 floats (x,y,z); 4th homogeneous comp is dropped
// by the reference.
// ---------------------------------------------------------------------------
__global__ void __launch_bounds__(TPTS) eval_kernel(
    const float4* __restrict__ ctrl,   // [B][64][64] float4
    float*        __restrict__ out)    // [B][256][256][3]
{
    const int i = blockIdx.x;
    const int b = blockIdx.y;
    const int j = threadIdx.x;

    __shared__ float4 sc[4][MCTRL];    // 4 control rows
    __shared__ float  wu_s[4];
    __shared__ int    row0_s;

    const int bi = b * TPTS + i;
    if (j == 0) {
        int r0 = g_span[bi] - DEG;
        r0 = r0 < 0 ? 0 : (r0 > MCTRL - 4 ? MCTRL - 4 : r0);
        row0_s = r0;
    }
    if (j < 4) wu_s[j] = g_basis[bi * 4 + j];
    __syncthreads();

    // Cooperative load: 4 rows x 64 cols = 256 float4, one per thread.
    {
        const int l = j >> 6;          // row within window
        const int cidx = j & 63;       // column
        sc[l][cidx] = ctrl[(b * MCTRL + row0_s + l) * MCTRL + cidx];
    }
    __syncthreads();

    // Per-thread column weights / span
    const int bj = b * TPTS + j;
    float wv[4];
    #pragma unroll
    for (int r = 0; r < 4; r++) wv[r] = g_basis[bj * 4 + r];
    int col0 = g_span[bj] - DEG;
    col0 = col0 < 0 ? 0 : (col0 > MCTRL - 4 ? MCTRL - 4 : col0);

    float x = 0.0f, y = 0.0f, z = 0.0f;
    #pragma unroll
    for (int l = 0; l < 4; l++) {
        const float wl = wu_s[l];
        #pragma unroll
        for (int r = 0; r < 4; r++) {
            const float w = wl * wv[r];
            const float4 cpt = sc[l][col0 + r];
            x = fmaf(w, cpt.x, x);
            y = fmaf(w, cpt.y, y);
            z = fmaf(w, cpt.z, z);
        }
    }

    const long long base = (((long long)bi) * TPTS + j) * 3;
    out[base + 0] = x;
    out[base + 1] = y;
    out[base + 2] = z;
}

// ---------------------------------------------------------------------------
// Launch
// ---------------------------------------------------------------------------
extern "C" void kernel_launch(void* const* d_in, const int* in_sizes, int n_in,
                              void* d_out, int out_size) {
    const float* ctrl   = (const float*)d_in[0];   // [16,64,64,4] f32
    const float* knot_u = (const float*)d_in[1];   // [16,68] f32
    // d_in[2] (knot_v) is unused: the reference builds V from knot_u too.
    (void)in_sizes; (void)n_in; (void)out_size;

    basis_kernel<<<BATCH, TPTS>>>(knot_u);
    eval_kernel<<<dim3(TPTS, BATCH), TPTS>>>((const float4*)ctrl, (float*)d_out);
}

// round 2
// speedup vs baseline: 1.2890x; 1.2890x over previous
#include <cuda_runtime.h>

// Problem constants (fixed by the reference)
#define BATCH 16
#define MCTRL 64          // control points per dim
#define DEG   3           // degree P == Q
#define KLEN  68          // MCTRL + DEG + 1 knots
#define NSPAN 62          // KLEN - 2*DEG candidate spans
#define TPTS  256         // OUT_U == OUT_V

// Scratch (no allocations allowed): basis [B][T][4], span [B][T]
__device__ float g_basis[BATCH * TPTS * 4];
__device__ int   g_span [BATCH * TPTS];

// ---------------------------------------------------------------------------
// Kernel 1: normalize knots (cumsum), find spans, Cox-de Boor basis (deg 3).
// One block per batch, one thread per eval point. Nv==Nu (reference reuses
// knot_u for V and u==v), so one table serves both directions.
// ---------------------------------------------------------------------------
__global__ void basis_kernel(const float* __restrict__ knot_u) {
    __shared__ float c[KLEN];   // cumsum
    __shared__ float U[KLEN];   // normalized knots
    const int b = blockIdx.x;
    const int t = threadIdx.x;

    if (t < KLEN) c[t] = knot_u[b * KLEN + t];
    __syncthreads();
    if (t == 0) {
        float s = 0.0f;
        for (int i = 0; i < KLEN; i++) { s += c[i]; c[i] = s; }
    }
    __syncthreads();
    {
        const float c0 = c[0];
        const float inv = 1.0f / (c[KLEN - 1] - c0);
        if (t < KLEN) U[t] = (c[t] - c0) * inv;
    }
    __syncthreads();

    // Parameter value: linspace(1e-5, 1-1e-5, 256)
    const float tp = 1e-5f + (float)t * ((1.0f - 2e-5f) / 255.0f);

    // Span: argmin over candidates (first minimum, like jnp.argmin)
    float best = 1e30f;
    int   bs   = 0;
    #pragma unroll 1
    for (int s = 0; s < NSPAN; s++) {
        float d    = tp - U[DEG + s];
        float cand = (d > 1e-8f) ? d : 1.0f;
        if (cand < best) { best = cand; bs = s; }
    }
    const int span = bs + DEG;

    // Cox-de Boor recursion, deg 3 — exactly the reference arithmetic.
    float N[DEG + 1];
    N[0] = 1.0f;
    #pragma unroll
    for (int k = 1; k <= DEG; k++) {
        float saved = 0.0f;
        #pragma unroll
        for (int r = 0; r < k; r++) {
            const float K1 = U[span + r + 1];
            const float K2 = U[span + 1 - k + r];
            const float temp = N[r] / ((K1 - tp) + (tp - K2));
            N[r] = saved + (K1 - tp) * temp;
            saved = (tp - K2) * temp;
        }
        N[k] = saved;
    }

    const int base = b * TPTS + t;
    #pragma unroll
    for (int l = 0; l <= DEG; l++) g_basis[base * 4 + l] = N[l];
    g_span[base] = span;
}

// ---------------------------------------------------------------------------
// Kernel 2: surface evaluation (separable form).
// Block = (i, b): one output row, 256 threads (one per j).
//   Stage 1: coop load the 4 needed control rows into smem (1 LDG.128/thread).
//   Stage 2: coop row-blend: blend[col] = sum_l wu[l] * sc[l][col]
//            (thread t -> col=t>>2, comp=t&3: 4 LDS.32 + 1 STS.32).
//   Stage 3: per j: out = sum_r wv[r] * blend[col0+r]  (4 LDS.128 only).
// This cuts per-output smem traffic ~3x vs the direct 16-point stencil.
// ---------------------------------------------------------------------------
__global__ void __launch_bounds__(TPTS) eval_kernel(
    const float4* __restrict__ ctrl,   // [B][64][64] float4
    float*        __restrict__ out)    // [B][256][256][3]
{
    const int i = blockIdx.x;
    const int b = blockIdx.y;
    const int j = threadIdx.x;

    __shared__ float4 sc[4][MCTRL];     // 4 control rows (4 KB)
    __shared__ float4 blend[MCTRL];     // row-blended control (1 KB)
    __shared__ float  wu_s[4];
    __shared__ int    row0_s;

    const int bi = b * TPTS + i;
    if (j == 0) {
        int r0 = g_span[bi] - DEG;
        r0 = r0 < 0 ? 0 : (r0 > MCTRL - 4 ? MCTRL - 4 : r0);
        row0_s = r0;
    }
    if (j < 4) wu_s[j] = g_basis[bi * 4 + j];
    __syncthreads();

    // Stage 1: cooperative load of 4 rows x 64 cols = 256 float4.
    {
        const int l = j >> 6;          // row within window
        const int cidx = j & 63;       // column
        sc[l][cidx] = ctrl[(b * MCTRL + row0_s + l) * MCTRL + cidx];
    }
    __syncthreads();

    // Stage 2: row blend. thread -> (col, comp). Conflict-free LDS.32/STS.32.
    {
        const int col  = j >> 2;
        const int comp = j & 3;
        const float* scf = (const float*)sc;        // [4][64][4] floats
        const float w0 = wu_s[0], w1 = wu_s[1], w2 = wu_s[2], w3 = wu_s[3];
        float acc;
        acc  = w0 * scf[(0 * MCTRL + col) * 4 + comp];
        acc  = fmaf(w1, scf[(1 * MCTRL + col) * 4 + comp], acc);
        acc  = fmaf(w2, scf[(2 * MCTRL + col) * 4 + comp], acc);
        acc  = fmaf(w3, scf[(3 * MCTRL + col) * 4 + comp], acc);
        ((float*)blend)[j] = acc;                   // blend[col].comp
    }
    __syncthreads();

    // Stage 3: per-output column stencil: 4 LDS.128 (mostly broadcast).
    const int bj = b * TPTS + j;
    float wv[4];
    #pragma unroll
    for (int r = 0; r < 4; r++) wv[r] = g_basis[bj * 4 + r];
    int col0 = g_span[bj] - DEG;
    col0 = col0 < 0 ? 0 : (col0 > MCTRL - 4 ? MCTRL - 4 : col0);

    float x = 0.0f, y = 0.0f, z = 0.0f;
    #pragma unroll
    for (int r = 0; r < 4; r++) {
        const float4 cpt = blend[col0 + r];
        x = fmaf(wv[r], cpt.x, x);
        y = fmaf(wv[r], cpt.y, y);
        z = fmaf(wv[r], cpt.z, z);
    }

    const long long base = (((long long)bi) * TPTS + j) * 3;
    out[base + 0] = x;
    out[base + 1] = y;
    out[base + 2] = z;
}

// ---------------------------------------------------------------------------
// Launch
// ---------------------------------------------------------------------------
extern "C" void kernel_launch(void* const* d_in, const int* in_sizes, int n_in,
                              void* d_out, int out_size) {
    const float* ctrl   = (const float*)d_in[0];   // [16,64,64,4] f32
    const float* knot_u = (const float*)d_in[1];   // [16,68] f32
    // d_in[2] (knot_v) is unused: the reference builds V from knot_u too.
    (void)in_sizes; (void)n_in; (void)out_size;

    basis_kernel<<<BATCH, TPTS>>>(knot_u);
    eval_kernel<<<dim3(TPTS, BATCH), TPTS>>>((const float4*)ctrl, (float*)d_out);
}

// round 3
// speedup vs baseline: 1.8221x; 1.4135x over previous
#include <cuda_runtime.h>

// Problem constants (fixed by the reference)
#define BATCH 16
#define MCTRL 64          // control points per dim
#define DEG   3           // degree P == Q
#define KLEN  68          // MCTRL + DEG + 1 knots
#define NSPAN 62          // KLEN - 2*DEG candidate spans
#define TPTS  256         // OUT_U == OUT_V
#define IPB   4           // output rows (i values) per block

// ---------------------------------------------------------------------------
// Per-thread basis: binary-search span + Cox-de Boor (deg 3), identical
// arithmetic to the reference. U is the normalized knot vector in smem.
// Span = argmin over candidates cand[s] = (tp-U[3+s] > 1e-8) ? tp-U[3+s] : 1.
// Since U[3..64] is strictly increasing, d is strictly decreasing in s, so
// the (unique) minimum is the LAST s with d > 1e-8 -> binary search.
// s=0 is always valid (tp >= 1e-5 >> U[3] ~ 5e-9).
// ---------------------------------------------------------------------------
__device__ __forceinline__ void basis_at(const float* __restrict__ U,
                                         float tp, float N[DEG + 1], int& span)
{
    int lo = 0, hi = NSPAN - 1;
    #pragma unroll
    for (int it = 0; it < 6; it++) {           // ceil(log2(62)) = 6
        const int mid = (lo + hi + 1) >> 1;
        if (lo < hi) {
            if (tp - U[DEG + mid] > 1e-8f) lo = mid; else hi = mid - 1;
        }
    }
    span = lo + DEG;

    N[0] = 1.0f;
    #pragma unroll
    for (int k = 1; k <= DEG; k++) {
        float saved = 0.0f;
        #pragma unroll
        for (int r = 0; r < k; r++) {
            const float K1 = U[span + r + 1];
            const float K2 = U[span + 1 - k + r];
            const float temp = N[r] / ((K1 - tp) + (tp - K2));
            N[r] = saved + (K1 - tp) * temp;
            saved = (tp - K2) * temp;
        }
        N[k] = saved;
    }
}

// ---------------------------------------------------------------------------
// Fused kernel. Block = (i-tile of IPB rows, batch b), 256 threads (one per j).
//   0) Hillis-Steele scan of the 68 knots -> normalized U (Nv==Nu: the
//      reference builds V from knot_u too, and u==v).
//   1) thread j: column basis wv[4]+col0; threads 0..IPB-1: row bases -> smem.
//   2) coop load IPB x 4 control rows (4 LDG.128/thread, MLP=4).
//   3) coop row-blend per i: blend[k][col] = sum_l wu[l]*rows[k][l][col].
//   4) per j, per k: out = sum_r wv[r]*blend[k][col0+r]  (4 LDS.128/output).
// ---------------------------------------------------------------------------
__global__ void __launch_bounds__(TPTS) fused_kernel(
    const float4* __restrict__ ctrl,     // [B][64][64] float4
    const float*  __restrict__ knot_u,   // [B][68]
    float*        __restrict__ out)      // [B][256][256][3]
{
    const int b  = blockIdx.y;
    const int i0 = blockIdx.x * IPB;
    const int j  = threadIdx.x;

    __shared__ float  U[KLEN];
    __shared__ float  scanA[KLEN], scanB[KLEN];
    __shared__ float4 rows [IPB][4][MCTRL];   // 16 KB
    __shared__ float4 blend[IPB][MCTRL];      //  4 KB
    __shared__ float  wu_s [IPB][4];
    __shared__ int    row0_s[IPB];

    // --- Stage 0: inclusive scan of knots, then normalize ---
    if (j < KLEN) scanA[j] = knot_u[b * KLEN + j];
    __syncthreads();
    {
        float* src = scanA;
        float* dst = scanB;
        #pragma unroll
        for (int off = 1; off < KLEN; off <<= 1) {     // 1,2,4,...,64 (7 steps)
            if (j < KLEN) dst[j] = (j >= off) ? src[j] + src[j - off] : src[j];
            __syncthreads();
            float* t = src; src = dst; dst = t;
        }
        if (j < KLEN) {
            const float c0 = src[0];
            U[j] = (src[j] - c0) / (src[KLEN - 1] - c0);
        }
    }
    __syncthreads();

    // --- Stage 1: bases ---
    const float step = (1.0f - 2e-5f) / 255.0f;

    // column basis for this thread's j
    float wv[DEG + 1];
    int   spanj;
    basis_at(U, 1e-5f + (float)j * step, wv, spanj);
    int col0 = spanj - DEG;
    col0 = col0 < 0 ? 0 : (col0 > MCTRL - 4 ? MCTRL - 4 : col0);

    // row bases for the IPB i's of this block
    if (j < IPB) {
        float wu[DEG + 1];
        int   spani;
        basis_at(U, 1e-5f + (float)(i0 + j) * step, wu, spani);
        int r0 = spani - DEG;
        r0 = r0 < 0 ? 0 : (r0 > MCTRL - 4 ? MCTRL - 4 : r0);
        row0_s[j] = r0;
        #pragma unroll
        for (int l = 0; l <= DEG; l++) wu_s[j][l] = wu[l];
    }
    __syncthreads();

    // --- Stage 2: cooperative row loads (IPB*4 rows x 64 cols) ---
    {
        const int l    = j >> 6;       // row within 4-row window
        const int cidx = j & 63;       // column
        #pragma unroll
        for (int k = 0; k < IPB; k++) {
            rows[k][l][cidx] = ctrl[(b * MCTRL + row0_s[k] + l) * MCTRL + cidx];
        }
    }
    __syncthreads();

    // --- Stage 3: row blends (thread -> (col, comp), conflict-free) ---
    {
        const int col  = j >> 2;
        const int comp = j & 3;
        const float* rf = (const float*)rows;   // [IPB][4][64][4] floats
        #pragma unroll
        for (int k = 0; k < IPB; k++) {
            const float w0 = wu_s[k][0], w1 = wu_s[k][1];
            const float w2 = wu_s[k][2], w3 = wu_s[k][3];
            const int base = ((k * 4) * MCTRL + col) * 4 + comp;
            float acc;
            acc = w0 * rf[base];
            acc = fmaf(w1, rf[base + 1 * MCTRL * 4], acc);
            acc = fmaf(w2, rf[base + 2 * MCTRL * 4], acc);
            acc = fmaf(w3, rf[base + 3 * MCTRL * 4], acc);
            ((float*)blend)[k * MCTRL * 4 + j] = acc;   // blend[k][col].comp
        }
    }
    __syncthreads();

    // --- Stage 4: column stencil + store (4 LDS.128 per output) ---
    #pragma unroll
    for (int k = 0; k < IPB; k++) {
        float x = 0.0f, y = 0.0f, z = 0.0f;
        #pragma unroll
        for (int r = 0; r < 4; r++) {
            const float4 cpt = blend[k][col0 + r];
            x = fmaf(wv[r], cpt.x, x);
            y = fmaf(wv[r], cpt.y, y);
            z = fmaf(wv[r], cpt.z, z);
        }
        const long long base =
            ((((long long)b * TPTS + (i0 + k)) * TPTS) + j) * 3;
        out[base + 0] = x;
        out[base + 1] = y;
        out[base + 2] = z;
    }
}

// ---------------------------------------------------------------------------
// Launch: single fused kernel (knot_v is unused — the reference builds V
// from knot_u as well).
// ---------------------------------------------------------------------------
extern "C" void kernel_launch(void* const* d_in, const int* in_sizes, int n_in,
                              void* d_out, int out_size) {
    const float* ctrl   = (const float*)d_in[0];   // [16,64,64,4] f32
    const float* knot_u = (const float*)d_in[1];   // [16,68] f32
    (void)in_sizes; (void)n_in; (void)out_size;

    fused_kernel<<<dim3(TPTS / IPB, BATCH), TPTS>>>(
        (const float4*)ctrl, knot_u, (float*)d_out);
}

// round 4
// speedup vs baseline: 2.1637x; 1.1875x over previous
#include <cuda_runtime.h>

// Problem constants (fixed by the reference)
#define BATCH 16
#define MCTRL 64          // control points per dim
#define DEG   3           // degree P == Q
#define KLEN  68          // MCTRL + DEG + 1 knots
#define NSPAN 62          // KLEN - 2*DEG candidate spans
#define TPTS  256         // OUT_U == OUT_V
#define IPB   4           // output rows (i values) per block

// ---------------------------------------------------------------------------
// Per-thread basis: binary-search span + Cox-de Boor (deg 3), identical
// arithmetic to the reference. U is the normalized knot vector in smem.
// Span = argmin over cand[s] = (tp-U[3+s] > 1e-8) ? tp-U[3+s] : 1.
// U[3..64] strictly increasing -> d strictly decreasing -> minimum is the
// LAST s with d > 1e-8 -> 6-step binary search. s=0 always valid.
// ---------------------------------------------------------------------------
__device__ __forceinline__ void basis_at(const float* __restrict__ U,
                                         float tp, float N[DEG + 1], int& span)
{
    int lo = 0, hi = NSPAN - 1;
    #pragma unroll
    for (int it = 0; it < 6; it++) {           // ceil(log2(62)) = 6
        const int mid = (lo + hi + 1) >> 1;
        if (lo < hi) {
            if (tp - U[DEG + mid] > 1e-8f) lo = mid; else hi = mid - 1;
        }
    }
    span = lo + DEG;

    N[0] = 1.0f;
    #pragma unroll
    for (int k = 1; k <= DEG; k++) {
        float saved = 0.0f;
        #pragma unroll
        for (int r = 0; r < k; r++) {
            const float K1 = U[span + r + 1];
            const float K2 = U[span + 1 - k + r];
            const float temp = N[r] / ((K1 - tp) + (tp - K2));
            N[r] = saved + (K1 - tp) * temp;
            saved = (tp - K2) * temp;
        }
        N[k] = saved;
    }
}

// 32-lane inclusive scan via shfl
__device__ __forceinline__ float warp_iscan(float v, int lane) {
    #pragma unroll
    for (int off = 1; off < 32; off <<= 1) {
        const float t = __shfl_up_sync(0xffffffffu, v, off);
        if (lane >= off) v += t;
    }
    return v;
}

// ---------------------------------------------------------------------------
// Fused kernel. Block = (i-tile of IPB rows, batch b), 256 threads (one per j).
//   0) warp-0 shuffle scan of the 68 knots -> normalized U in smem
//      (Nv==Nu: the reference builds V from knot_u too, and u==v).
//   1) thread j: column basis wv[4]+col0; threads 0..IPB-1: row bases.
//   2) row blend DIRECTLY from global (coalesced LDG.32, L2-resident ctrl):
//      thread (col,comp): blend[k][col].comp = sum_l wu[k][l]*ctrl[row0+l][col].comp
//   3) per j, per k: out = sum_r wv[r]*blend[k][col0+r]  (4 LDS.128/output).
// ---------------------------------------------------------------------------
__global__ void __launch_bounds__(TPTS) fused_kernel(
    const float4* __restrict__ ctrl,     // [B][64][64] float4
    const float*  __restrict__ knot_u,   // [B][68]
    float*        __restrict__ out)      // [B][256][256][3]
{
    const int b  = blockIdx.y;
    const int i0 = blockIdx.x * IPB;
    const int j  = threadIdx.x;

    __shared__ float  U[KLEN];
    __shared__ float4 blend[IPB][MCTRL];      // 4 KB
    __shared__ float  wu_s [IPB][4];
    __shared__ int    row0_s[IPB];

    // --- Stage 0: warp-0 scan of knots + normalize ---
    if (j < 32) {
        const float* kb = knot_u + b * KLEN;
        float a0 = kb[j];
        float a1 = kb[j + 32];
        float a2 = (j < KLEN - 64) ? kb[j + 64] : 0.0f;
        const float k0 = __shfl_sync(0xffffffffu, a0, 0);  // knot[0] == cumsum[0]

        a0 = warp_iscan(a0, j);
        const float tot0 = __shfl_sync(0xffffffffu, a0, 31);
        a1 = warp_iscan(a1, j) + tot0;
        const float tot1 = __shfl_sync(0xffffffffu, a1, 31);
        a2 = warp_iscan(a2, j) + tot1;

        const float last = __shfl_sync(0xffffffffu, a2, KLEN - 64 - 1); // c[67]
        const float inv  = 1.0f / (last - k0);
        U[j]      = (a0 - k0) * inv;
        U[j + 32] = (a1 - k0) * inv;
        if (j < KLEN - 64) U[j + 64] = (a2 - k0) * inv;
    }
    __syncthreads();

    // --- Stage 1: bases ---
    const float step = (1.0f - 2e-5f) / 255.0f;

    float wv[DEG + 1];
    int   spanj;
    basis_at(U, 1e-5f + (float)j * step, wv, spanj);
    int col0 = spanj - DEG;
    col0 = col0 < 0 ? 0 : (col0 > MCTRL - 4 ? MCTRL - 4 : col0);

    if (j < IPB) {
        float wu[DEG + 1];
        int   spani;
        basis_at(U, 1e-5f + (float)(i0 + j) * step, wu, spani);
        int r0 = spani - DEG;
        r0 = r0 < 0 ? 0 : (r0 > MCTRL - 4 ? MCTRL - 4 : r0);
        row0_s[j] = r0;
        #pragma unroll
        for (int l = 0; l <= DEG; l++) wu_s[j][l] = wu[l];
    }
    __syncthreads();

    // --- Stage 2: row blends straight from global ---
    // thread j <-> (col = j>>2, comp = j&3); float offset col*4+comp == j,
    // so each row read is a fully-coalesced 128B warp transaction (L2 hit).
    {
        const float* cbase = (const float*)ctrl + (size_t)b * MCTRL * MCTRL * 4;
        #pragma unroll
        for (int k = 0; k < IPB; k++) {
            const float* rp = cbase + (size_t)row0_s[k] * (MCTRL * 4) + j;
            const float w0 = wu_s[k][0], w1 = wu_s[k][1];
            const float w2 = wu_s[k][2], w3 = wu_s[k][3];
            float acc;
            acc = w0 * rp[0];
            acc = fmaf(w1, rp[1 * MCTRL * 4], acc);
            acc = fmaf(w2, rp[2 * MCTRL * 4], acc);
            acc = fmaf(w3, rp[3 * MCTRL * 4], acc);
            ((float*)blend)[k * MCTRL * 4 + j] = acc;   // blend[k][col].comp
        }
    }
    __syncthreads();

    // --- Stage 3: column stencil + store (4 LDS.128 per output) ---
    #pragma unroll
    for (int k = 0; k < IPB; k++) {
        float x = 0.0f, y = 0.0f, z = 0.0f;
        #pragma unroll
        for (int r = 0; r < 4; r++) {
            const float4 cpt = blend[k][col0 + r];
            x = fmaf(wv[r], cpt.x, x);
            y = fmaf(wv[r], cpt.y, y);
            z = fmaf(wv[r], cpt.z, z);
        }
        const long long base =
            ((((long long)b * TPTS + (i0 + k)) * TPTS) + j) * 3;
        out[base + 0] = x;
        out[base + 1] = y;
        out[base + 2] = z;
    }
}

// ---------------------------------------------------------------------------
// Launch: single fused kernel (knot_v is unused — the reference builds V
// from knot_u as well).
// ---------------------------------------------------------------------------
extern "C" void kernel_launch(void* const* d_in, const int* in_sizes, int n_in,
                              void* d_out, int out_size) {
    const float* ctrl   = (const float*)d_in[0];   // [16,64,64,4] f32
    const float* knot_u = (const float*)d_in[1];   // [16,68] f32
    (void)in_sizes; (void)n_in; (void)out_size;

    fused_kernel<<<dim3(TPTS / IPB, BATCH), TPTS>>>(
        (const float4*)ctrl, knot_u, (float*)d_out);
}